// round 14
// baseline (speedup 1.0000x reference)
#include <cuda_runtime.h>
#include <cstdint>

// Problem dims
#define BB      128
#define TT      512
#define UU      128
#define NW      80
#define HH      512
#define MM      10
#define GRID    128
#define BLOCK   512
#define OUT_STRIDE 593
#define NKKT    320                     // packed k-pair rows (640 k)
#define CHUNK_BYTES 16384               // 16 kk x 128 b x 8 B
#define GBUF_FLOATS (20 * CHUNK_BYTES / 4)   // 81920 floats per buffer

// ---------------- device global state ----------------
// g_inp[buf][chunk][kk_local][b][2]: k 0..511 = h, 512..591 = w, 592..594 = x, rest 0.
__device__ __align__(128) float g_inp[2 * GBUF_FLOATS];
__device__ float g_kappa[BB * MM];
__device__ unsigned int g_bar;
__device__ unsigned int g_wdone;
__device__ unsigned int g_hdone;

// ---------------- helpers ----------------
__device__ __forceinline__ void unpack2(unsigned long long v, float &lo, float &hi) {
    asm("mov.b64 {%0, %1}, %2;" : "=f"(lo), "=f"(hi) : "l"(v));
}
__device__ __forceinline__ void ffma2(unsigned long long &d, unsigned long long a,
                                      unsigned long long b) {
    asm("fma.rn.f32x2 %0, %1, %2, %0;" : "+l"(d) : "l"(a), "l"(b));
}
__device__ __forceinline__ float sigf(float x) {
    return __fdividef(1.f, 1.f + __expf(-x));
}
// byte offset of element (b, k) inside one A buffer
__device__ __forceinline__ int a_idx(int b, int k) {
    return (k >> 5) * CHUNK_BYTES + ((k >> 1) & 15) * 1024 + b * 8 + (k & 1) * 4;
}
__device__ __forceinline__ void issue_chunk(uint32_t mbar, uint32_t sdst,
                                            const void* gsrc) {
    asm volatile("mbarrier.arrive.expect_tx.shared::cta.b64 _, [%0], %1;"
                 :: "r"(mbar), "r"((uint32_t)CHUNK_BYTES) : "memory");
    asm volatile("cp.async.bulk.shared::cta.global.mbarrier::complete_tx::bytes "
                 "[%0], [%1], %2, [%3];"
                 :: "r"(sdst), "l"(gsrc), "r"((uint32_t)CHUNK_BYTES), "r"(mbar)
                 : "memory");
}
__device__ __forceinline__ void mbar_wait(uint32_t mbar, int parity) {
    asm volatile(
        "{\n\t.reg .pred P;\n\tLAB_%=:\n\t"
        "mbarrier.try_wait.parity.acquire.cta.shared::cta.b64 P, [%0], %1, 0x989680;\n\t"
        "@!P bra LAB_%=;\n\t}"
        :: "r"(mbar), "r"((unsigned)parity) : "memory");
}
__device__ __forceinline__ void poll_ge(volatile unsigned int* p, unsigned int tgt) {
    while (*p < tgt) { }
    __threadfence();
}

// ---------------- init kernel ----------------
__global__ void rnn_init_kernel() {
    int tid = blockIdx.x * blockDim.x + threadIdx.x;
    int nthr = gridDim.x * blockDim.x;
    for (int i = tid; i < 2 * GBUF_FLOATS; i += nthr) g_inp[i] = 0.f;
    for (int i = tid; i < BB * MM; i += nthr) g_kappa[i] = 0.f;
    if (tid == 0) { g_bar = 0u; g_wdone = 0u; g_hdone = 0u; }
}

// ---------------- smem layout ----------------
#define OFF_MBAR  0        // 6 mbarriers (8B each)
#define OFF_BIAS  64       // 16 floats
#define OFF_WP    1024     // 320*32 floats = 40960 B
#define OFF_WD    41984    // 512*30 floats = 61440 B
#define OFF_AIN   103424   // 6 x 16384 = 98304 B staging (sZ aliases buffer 0)
#define OFF_H     201728   // 512 floats = 2048
#define OFF_YP    203776   // 480 floats = 1920
#define OFF_WF    205696   // 136 floats = 544
#define OFF_Y     206240   // 128
#define OFF_BD    206368   // 128
#define OFF_A2    206496   // 64
#define OFF_BE2   206560   // 64
#define OFF_KA2   206624   // 64
#define SMEM_BYTES 206720

extern __shared__ char smem_raw[];

__global__ void __launch_bounds__(BLOCK, 1)
rnn_persistent_kernel(const float* __restrict__ strokes,
                      const float* __restrict__ trans,
                      const float* __restrict__ Wx,
                      const float* __restrict__ Wh,
                      const float* __restrict__ bvec,
                      const float* __restrict__ Wd,
                      const float* __restrict__ bd,
                      float* __restrict__ out) {
    float* sWp   = (float*)(smem_raw + OFF_WP);   // [320 kk][4 cg][4 gate][2 lane]
    float* sWd   = (float*)(smem_raw + OFF_WD);   // [512][30]
    unsigned long long* sZ = (unsigned long long*)(smem_raw + OFF_AIN); // alias buf h0/0
    float* s_h   = (float*)(smem_raw + OFF_H);
    float* s_yp  = (float*)(smem_raw + OFF_YP);
    float* s_wf  = (float*)(smem_raw + OFF_WF);
    float* s_y   = (float*)(smem_raw + OFF_Y);
    float* s_bd  = (float*)(smem_raw + OFF_BD);
    float* s_a   = (float*)(smem_raw + OFF_A2);
    float* s_be  = (float*)(smem_raw + OFF_BE2);
    float* s_ka  = (float*)(smem_raw + OFF_KA2);
    float* sBias = (float*)(smem_raw + OFF_BIAS); // [4 cg][4 gate]

    const uint32_t smem_base = (uint32_t)__cvta_generic_to_shared(smem_raw);

    const int tid  = threadIdx.x;
    const int wid  = tid >> 5;
    const int lid  = tid & 31;
    const int half = wid >> 3;           // k-half: 0 -> k<320, 1 -> k>=320
    const int cg   = lid >> 3;           // owned h-col within CTA (0..3)
    const int bgrp = lid & 7;
    const int bloc = (wid & 7) * 16 + bgrp * 2;   // first of 2 owned batch rows
    const int bb   = blockIdx.x;         // CTA == batch row in attention phase
    const int j0   = blockIdx.x * 4;     // owned h-columns [j0, j0+4)
    const bool isdma = (tid == 0) || (tid == 256);

    const int base = half * 10;          // first chunk index of this half
    // this half's 3 ring buffers
    const uint32_t mb_0 = smem_base + OFF_MBAR + (half * 3 + 0) * 8;
    const uint32_t mb_1 = mb_0 + 8;
    const uint32_t mb_2 = mb_0 + 16;
    const uint32_t dst_0 = smem_base + OFF_AIN + (half * 3 + 0) * CHUNK_BYTES;
    const uint32_t dst_1 = dst_0 + CHUNK_BYTES;
    const uint32_t dst_2 = dst_0 + 2 * CHUNK_BYTES;
    const char* sbb_0 = smem_raw + OFF_AIN + (half * 3 + 0) * CHUNK_BYTES + bloc * 8;
    const char* sbb_1 = sbb_0 + CHUNK_BYTES;
    const char* sbb_2 = sbb_0 + 2 * CHUNK_BYTES;

    // ---- mbarrier init ----
    if (tid == 0) {
#pragma unroll
        for (int m = 0; m < 6; ++m)
            asm volatile("mbarrier.init.shared.b64 [%0], 1;"
                         :: "r"(smem_base + OFF_MBAR + m * 8) : "memory");
        asm volatile("fence.proxy.async.shared::cta;" ::: "memory");
    }

    // ---- one-time weight staging ----
    // sWp[kk][cg][gate][lane]: lane 0 = even k (2kk), lane 1 = odd k (2kk+1)
    for (int i = tid; i < NKKT * 32; i += BLOCK) {
        int kk = i >> 5, rem = i & 31;
        int c_ = rem >> 3, e = rem & 7, gate = e >> 1, lane = e & 1;
        int col = (gate << 9) + j0 + c_;
        int k = 2 * kk + lane;
        float val;
        if (k < HH)                 val = Wh[k * 2048 + col];
        else if (k < HH + NW)       val = Wx[(3 + k - HH) * 2048 + col];
        else if (k < HH + NW + 3)   val = Wx[(k - (HH + NW)) * 2048 + col];
        else                        val = 0.f;
        sWp[i] = val;
    }
    if (tid < 16) {
        int c_ = tid >> 2, gate = tid & 3;
        sBias[tid] = bvec[(gate << 9) + j0 + c_];
    }
    for (int i = tid; i < HH * 30; i += BLOCK) sWd[i] = Wd[i];
    if (tid < 30) s_bd[tid] = bd[tid];
    __syncthreads();

    // prologue: write x_0 for own batch row, make globally visible (one-time barrier)
    if (tid < 3) {
        *(float*)((char*)g_inp + a_idx(bb, HH + NW + tid)) =
            strokes[(size_t)bb * TT * 3 + tid];
    }
    __threadfence();
    __syncthreads();
    if (tid == 0) {
        atomicAdd(&g_bar, 1u);
        volatile unsigned int* vp = &g_bar;
        while (*vp < GRID) { }
        __threadfence();
    }
    __syncthreads();

    // prime first 3 chunks of each half for t=0
    if (isdma) {
        issue_chunk(mb_0, dst_0, (const char*)g_inp + (base + 0) * CHUNK_BYTES);
        issue_chunk(mb_1, dst_1, (const char*)g_inp + (base + 1) * CHUNK_BYTES);
        issue_chunk(mb_2, dst_2, (const char*)g_inp + (base + 2) * CHUNK_BYTES);
    }

    float c0 = 0.f, c1 = 0.f;            // LSTM c-state (half 0 lanes only)

    for (int t = 0; t < TT; ++t) {
        const char* gin   = (const char*)(g_inp + (t & 1) * GBUF_FLOATS);
        char*       gnext = (char*)(g_inp + ((t + 1) & 1) * GBUF_FLOATS);

        // ===== Phase A: 8 FFMA2 per kk per lane (2 b x 4 gates), own k-half =====
        unsigned long long a00 = 0, a01 = 0, a02 = 0, a03 = 0;  // batch b
        unsigned long long a10 = 0, a11 = 0, a12 = 0, a13 = 0;  // batch b+1

        // rotating ring state (buffer order 0,1,2,0,1,2,...)
        uint32_t m0 = mb_0, m1 = mb_1, m2 = mb_2;
        uint32_t d0 = dst_0, d1 = dst_1, d2 = dst_2;
        const char *s0 = sbb_0, *s1 = sbb_1, *s2 = sbb_2;
        int pa = 0, pb = t & 1, pc = t & 1;

        const unsigned int wtarget = (unsigned int)t * GRID;

        for (int ci = 0; ci < 10; ++ci) {
            mbar_wait(m0, pa);

            const float* wr0 = sWp + ((base + ci) << 4) * 32 + cg * 8;
            const char* sb = s0;
#pragma unroll 4
            for (int j = 0; j < 16; ++j) {
                ulonglong2 vv = *(const ulonglong2*)(sb + j * 1024);
                const ulonglong2* wr = (const ulonglong2*)(wr0 + j * 32);
                ulonglong2 wlo = wr[0], whi = wr[1];   // gates (i,f), (g,o)
                ffma2(a00, vv.x, wlo.x); ffma2(a01, vv.x, wlo.y);
                ffma2(a02, vv.x, whi.x); ffma2(a03, vv.x, whi.y);
                ffma2(a10, vv.y, wlo.x); ffma2(a11, vv.y, wlo.y);
                ffma2(a12, vv.y, whi.x); ffma2(a13, vv.y, whi.y);
            }
            asm volatile("bar.sync %0, 256;" :: "r"(1 + half) : "memory");

            if (ci <= 6 && isdma) {
                if (half == 1 && ci == 3) {
                    // chunks >=16 carry w_{t-1}, x_t from all CTAs' phase C(t-1)
                    poll_ge(&g_wdone, wtarget);
                }
                issue_chunk(m0, d0, gin + (base + ci + 3) * CHUNK_BYTES);
            }
            // rotate ring: used buffer goes to back with flipped parity
            uint32_t tm = m0; m0 = m1; m1 = m2; m2 = tm;
            uint32_t td = d0; d0 = d1; d1 = d2; d2 = td;
            const char* ts = s0; s0 = s1; s1 = s2; s2 = ts;
            int tp = pa ^ 1; pa = pb; pb = pc; pc = tp;
        }

        // join halves before reusing half0/buf0 smem as the z-exchange area
        __syncthreads();

        // ===== z exchange: half1 stores partials, half0 reduces + LSTM =====
        if (half == 1) {
            unsigned long long* zp = sZ + bloc * 16 + cg * 4;
            zp[0] = a00; zp[1] = a01; zp[2] = a02; zp[3] = a03;
            zp += 16;
            zp[0] = a10; zp[1] = a11; zp[2] = a12; zp[3] = a13;
        }
        __syncthreads();

        if (half == 0) {
            const unsigned long long* zp = sZ + bloc * 16 + cg * 4;
            float lo, hi, l2, h2;
#define REDZ(acc, part, bias, dst) { unpack2(acc, lo, hi); unpack2(part, l2, h2); \
            dst = ((lo + l2) + (hi + h2)) + bias; }
            float zi, zf, zg, zo;
            float bi_ = sBias[cg * 4 + 0], bf_ = sBias[cg * 4 + 1];
            float bg_ = sBias[cg * 4 + 2], bo_ = sBias[cg * 4 + 3];

            REDZ(a00, zp[0], bi_, zi); REDZ(a01, zp[1], bf_, zf);
            REDZ(a02, zp[2], bg_, zg); REDZ(a03, zp[3], bo_, zo);
            float cn = sigf(zf) * c0 + sigf(zi) * tanhf(zg);
            float hn = sigf(zo) * tanhf(cn); c0 = cn;
            out[((size_t)bloc * TT + t) * OUT_STRIDE + j0 + cg] = hn;
            *(float*)(gnext + a_idx(bloc, j0 + cg)) = hn;

            zp += 16;
            REDZ(a10, zp[0], bi_, zi); REDZ(a11, zp[1], bf_, zf);
            REDZ(a12, zp[2], bg_, zg); REDZ(a13, zp[3], bo_, zo);
            cn = sigf(zf) * c1 + sigf(zi) * tanhf(zg);
            hn = sigf(zo) * tanhf(cn); c1 = cn;
            out[((size_t)(bloc + 1) * TT + t) * OUT_STRIDE + j0 + cg] = hn;
            *(float*)(gnext + a_idx(bloc + 1, j0 + cg)) = hn;
#undef REDZ
        }
        __threadfence();
        __syncthreads();

        // release h(t); DMA threads wait for all CTAs' h, then prime step t+1
        if (tid == 0) {
            atomicAdd(&g_hdone, 1u);
            poll_ge(&g_hdone, (unsigned int)(t + 1) * GRID);
            if (t + 1 < TT) {
                issue_chunk(mb_0, dst_0, gnext + (base + 0) * CHUNK_BYTES);
                issue_chunk(mb_1, dst_1, gnext + (base + 1) * CHUNK_BYTES);
                issue_chunk(mb_2, dst_2, gnext + (base + 2) * CHUNK_BYTES);
            }
        } else if (tid == 256 && t + 1 < TT) {
            poll_ge(&g_hdone, (unsigned int)(t + 1) * GRID);
            issue_chunk(mb_0, dst_0, gnext + (base + 0) * CHUNK_BYTES);
            issue_chunk(mb_1, dst_1, gnext + (base + 1) * CHUNK_BYTES);
            issue_chunk(mb_2, dst_2, gnext + (base + 2) * CHUNK_BYTES);
        }
        __syncthreads();                 // all threads now see h(t) globally done

        // ===== Phase C: attention head for batch row bb (overlaps t+1 DMA) =====
        {
            float* orow = out + ((size_t)bb * TT + t) * OUT_STRIDE;

            s_h[tid] = orow[tid];        // BLOCK == HH
            __syncthreads();

            // y = h @ Wd  (30 outputs, 16-way K split over 480 threads)
            if (tid < 480) {
                int n = tid >> 4, q = tid & 15;
                int k0 = q * 32;
                float p0 = 0.f, p1 = 0.f, p2 = 0.f, p3 = 0.f;
#pragma unroll 4
                for (int k = k0; k < k0 + 32; k += 4) {
                    p0 = fmaf(s_h[k],     sWd[(k)     * 30 + n], p0);
                    p1 = fmaf(s_h[k + 1], sWd[(k + 1) * 30 + n], p1);
                    p2 = fmaf(s_h[k + 2], sWd[(k + 2) * 30 + n], p2);
                    p3 = fmaf(s_h[k + 3], sWd[(k + 3) * 30 + n], p3);
                }
                s_yp[tid] = (p0 + p1) + (p2 + p3);
            }
            __syncthreads();
            if (tid < 30) {
                float s = 0.f;
#pragma unroll
                for (int q = 0; q < 16; ++q) s += s_yp[tid * 16 + q];
                s_y[tid] = __expf(s + s_bd[tid]);
            }
            __syncthreads();
            if (tid < MM) {
                float ka = g_kappa[bb * MM + tid] + s_y[20 + tid];
                g_kappa[bb * MM + tid] = ka;
                s_ka[tid] = ka;
                s_a[tid]  = s_y[tid];
                s_be[tid] = s_y[10 + tid];
            }
            __syncthreads();

            if (tid <= UU) {
                float fu = (float)tid, acc = 0.f;
#pragma unroll
                for (int m = 0; m < MM; ++m) {
                    float d = s_ka[m] - fu;
                    acc = fmaf(s_a[m], __expf(-s_be[m] * d * d), acc);
                }
                s_wf[tid] = acc;
            }
            __syncthreads();

            if (tid < 32) {              // argmax, first-max tie rule
                float bv = -3.4e38f; int bi = 0;
                for (int u = tid; u <= UU; u += 32) {
                    float v = s_wf[u];
                    if (v > bv) { bv = v; bi = u; }
                }
                for (int off = 16; off; off >>= 1) {
                    float ov = __shfl_xor_sync(0xffffffffu, bv, off);
                    int   oi = __shfl_xor_sync(0xffffffffu, bi, off);
                    if (ov > bv || (ov == bv && oi < bi)) { bv = ov; bi = oi; }
                }
                if (tid == 0) orow[HH + NW] = (float)bi;
            }

            // w = wfull[:U] @ transcriptions[bb]   (trans from L2)
            if (tid < NW) {
                const float* tr = trans + (size_t)bb * UU * NW + tid;
                float a0 = 0.f, a1 = 0.f, a2 = 0.f, a3 = 0.f;
#pragma unroll 4
                for (int u = 0; u < UU; u += 4) {
                    a0 = fmaf(s_wf[u],     tr[(u)     * NW], a0);
                    a1 = fmaf(s_wf[u + 1], tr[(u + 1) * NW], a1);
                    a2 = fmaf(s_wf[u + 2], tr[(u + 2) * NW], a2);
                    a3 = fmaf(s_wf[u + 3], tr[(u + 3) * NW], a3);
                }
                float wv = (a0 + a1) + (a2 + a3);
                *(float*)(gnext + a_idx(bb, HH + tid)) = wv;
                orow[HH + tid] = wv;
            }

            // x_{t+1} for own row
            if (t + 1 < TT && tid < 3) {
                *(float*)(gnext + a_idx(bb, HH + NW + tid)) =
                    strokes[(size_t)bb * TT * 3 + (t + 1) * 3 + tid];
            }

            __syncthreads();
            if (tid == 0) {              // signal w_t / x_{t+1} ready
                __threadfence();
                atomicAdd(&g_wdone, 1u);
            }
        }
    }
}

// ---------------- launch ----------------
extern "C" void kernel_launch(void* const* d_in, const int* in_sizes, int n_in,
                              void* d_out, int out_size) {
    const float* strokes = (const float*)d_in[0];
    const float* trans   = (const float*)d_in[1];
    // d_in[2] = enumerated -- recomputed on the fly
    const float* Wx      = (const float*)d_in[3];
    const float* Wh      = (const float*)d_in[4];
    const float* bvec    = (const float*)d_in[5];
    const float* Wd      = (const float*)d_in[6];
    const float* bd      = (const float*)d_in[7];
    float* out = (float*)d_out;

    cudaFuncSetAttribute(rnn_persistent_kernel,
                         cudaFuncAttributeMaxDynamicSharedMemorySize, SMEM_BYTES);

    rnn_init_kernel<<<32, 256>>>();
    rnn_persistent_kernel<<<GRID, BLOCK, SMEM_BYTES>>>(strokes, trans, Wx, Wh,
                                                       bvec, Wd, bd, out);
}

// round 17
// speedup vs baseline: 1.5599x; 1.5599x over previous
#include <cuda_runtime.h>
#include <cstdint>

// Problem dims
#define BB      128
#define TT      512
#define UU      128
#define NW      80
#define HH      512
#define MM      10
#define GRID    128
#define BLOCK   544                     // 16 compute warps + 1 DMA warp
#define OUT_STRIDE 593
#define NKKT    320                     // packed k-pair rows (640 k)
#define CHUNK_BYTES 16384               // 16 kk x 128 b x 8 B
#define GBUF_FLOATS (20 * CHUNK_BYTES / 4)   // 81920 floats per buffer

// ---------------- device global state ----------------
// g_inp[buf][chunk][kk_local][b][2]: k 0..511 = h, 512..591 = w, 592..594 = x, rest 0.
__device__ __align__(128) float g_inp[2 * GBUF_FLOATS];
__device__ float g_kappa[BB * MM];
__device__ unsigned int g_bar;
__device__ unsigned int g_wdone;

// ---------------- helpers ----------------
__device__ __forceinline__ void unpack2(unsigned long long v, float &lo, float &hi) {
    asm("mov.b64 {%0, %1}, %2;" : "=f"(lo), "=f"(hi) : "l"(v));
}
__device__ __forceinline__ void ffma2(unsigned long long &d, unsigned long long a,
                                      unsigned long long b) {
    asm("fma.rn.f32x2 %0, %1, %2, %0;" : "+l"(d) : "l"(a), "l"(b));
}
__device__ __forceinline__ float sigf(float x) {
    return __fdividef(1.f, 1.f + __expf(-x));
}
// byte offset of element (b, k) inside one A buffer
__device__ __forceinline__ int a_idx(int b, int k) {
    return (k >> 5) * CHUNK_BYTES + ((k >> 1) & 15) * 1024 + b * 8 + (k & 1) * 4;
}
__device__ __forceinline__ void issue_chunk(uint32_t mbar, uint32_t sdst,
                                            const void* gsrc) {
    asm volatile("mbarrier.arrive.expect_tx.shared::cta.b64 _, [%0], %1;"
                 :: "r"(mbar), "r"((uint32_t)CHUNK_BYTES) : "memory");
    asm volatile("cp.async.bulk.shared::cta.global.mbarrier::complete_tx::bytes "
                 "[%0], [%1], %2, [%3];"
                 :: "r"(sdst), "l"(gsrc), "r"((uint32_t)CHUNK_BYTES), "r"(mbar)
                 : "memory");
}
__device__ __forceinline__ void mbar_wait(uint32_t mbar, int parity) {
    asm volatile(
        "{\n\t.reg .pred P;\n\tLAB_%=:\n\t"
        "mbarrier.try_wait.parity.acquire.cta.shared::cta.b64 P, [%0], %1, 0x989680;\n\t"
        "@!P bra LAB_%=;\n\t}"
        :: "r"(mbar), "r"((unsigned)parity) : "memory");
}
__device__ __forceinline__ bool mbar_test(uint32_t mbar, int parity) {
    uint32_t r;
    asm volatile(
        "{\n\t.reg .pred P;\n\t"
        "mbarrier.test_wait.parity.shared.b64 P, [%1], %2;\n\t"
        "selp.b32 %0, 1, 0, P;\n\t}"
        : "=r"(r) : "r"(mbar), "r"((unsigned)parity) : "memory");
    return r != 0;
}
__device__ __forceinline__ void mbar_arrive(uint32_t mbar) {
    asm volatile("mbarrier.arrive.shared.b64 _, [%0];" :: "r"(mbar) : "memory");
}
__device__ __forceinline__ void grid_barrier(unsigned int target) {
    __threadfence();
    __syncthreads();
    if (threadIdx.x == 0) {
        atomicAdd(&g_bar, 1u);
        volatile unsigned int* vp = &g_bar;
        while (*vp < target) { }
        __threadfence();
    }
    __syncthreads();
}

// ---------------- init kernel ----------------
__global__ void rnn_init_kernel() {
    int tid = blockIdx.x * blockDim.x + threadIdx.x;
    int nthr = gridDim.x * blockDim.x;
    for (int i = tid; i < 2 * GBUF_FLOATS; i += nthr) g_inp[i] = 0.f;
    for (int i = tid; i < BB * MM; i += nthr) g_kappa[i] = 0.f;
    if (tid == 0) { g_bar = 0u; g_wdone = 0u; }
}

// ---------------- smem layout ----------------
#define OFF_MBAR  0        // full[4] @0..31, free[4] @32..63
#define OFF_BIAS  64       // 16 floats
#define OFF_WP    1024     // 320*32 floats = 40960 B
#define OFF_WD    41984    // 512*30 floats = 61440 B
#define OFF_AIN   103424   // 4 x 16384 = 65536 B staging
#define OFF_Z     168960   // 128*16 ulonglong = 16384 B
#define OFF_H     185344   // 512 floats
#define OFF_YP    187392   // 480 floats
#define OFF_WF    189312   // 136 floats
#define OFF_Y     189856   // 32 floats
#define OFF_BD    189984   // 32 floats
#define OFF_A2    190112   // 16 floats
#define OFF_BE2   190176   // 16 floats
#define OFF_KA2   190240   // 16 floats
#define SMEM_BYTES 190336

extern __shared__ char smem_raw[];

__global__ void __launch_bounds__(BLOCK, 1)
rnn_persistent_kernel(const float* __restrict__ strokes,
                      const float* __restrict__ trans,
                      const float* __restrict__ Wx,
                      const float* __restrict__ Wh,
                      const float* __restrict__ bvec,
                      const float* __restrict__ Wd,
                      const float* __restrict__ bd,
                      float* __restrict__ out) {
    float* sWp   = (float*)(smem_raw + OFF_WP);   // [320 kk][4 cg][4 gate][2 lane]
    float* sWd   = (float*)(smem_raw + OFF_WD);   // [512][30]
    unsigned long long* sZ = (unsigned long long*)(smem_raw + OFF_Z); // [128 b][16]
    float* s_h   = (float*)(smem_raw + OFF_H);
    float* s_yp  = (float*)(smem_raw + OFF_YP);
    float* s_wf  = (float*)(smem_raw + OFF_WF);
    float* s_y   = (float*)(smem_raw + OFF_Y);
    float* s_bd  = (float*)(smem_raw + OFF_BD);
    float* s_a   = (float*)(smem_raw + OFF_A2);
    float* s_be  = (float*)(smem_raw + OFF_BE2);
    float* s_ka  = (float*)(smem_raw + OFF_KA2);
    float* sBias = (float*)(smem_raw + OFF_BIAS); // [4 cg][4 gate]

    const uint32_t smem_base = (uint32_t)__cvta_generic_to_shared(smem_raw);

    const int tid  = threadIdx.x;
    const int wid  = tid >> 5;
    const int lid  = tid & 31;
    const bool isC = (wid < 16);         // compute warp?
    const int half = isC ? (wid >> 3) : 0;   // k-half: 0 -> k<320, 1 -> k>=320
    const int cg   = lid >> 3;           // owned h-col within CTA (0..3)
    const int bgrp = lid & 7;
    const int bloc = (wid & 7) * 16 + bgrp * 2;   // first of 2 owned batch rows
    const int bb   = blockIdx.x;         // CTA == batch row in attention phase
    const int j0   = blockIdx.x * 4;     // owned h-columns [j0, j0+4)

    // mbarrier addresses: full[h*2+s], free[h*2+s]
    const uint32_t MB = smem_base + OFF_MBAR;
#define FU(h, s) (MB + ((h) * 2 + (s)) * 8)
#define FR(h, s) (MB + 32 + ((h) * 2 + (s)) * 8)

    // ---- mbarrier init ----
    if (tid == 0) {
#pragma unroll
        for (int m = 0; m < 4; ++m) {
            asm volatile("mbarrier.init.shared.b64 [%0], 1;"
                         :: "r"(MB + m * 8) : "memory");
            asm volatile("mbarrier.init.shared.b64 [%0], 256;"
                         :: "r"(MB + 32 + m * 8) : "memory");
        }
        asm volatile("fence.proxy.async.shared::cta;" ::: "memory");
    }

    // ---- one-time weight staging ----
    // sWp[kk][cg][gate][lane]: lane 0 = even k (2kk), lane 1 = odd k (2kk+1)
    for (int i = tid; i < NKKT * 32; i += BLOCK) {
        int kk = i >> 5, rem = i & 31;
        int c_ = rem >> 3, e = rem & 7, gate = e >> 1, lane = e & 1;
        int col = (gate << 9) + j0 + c_;
        int k = 2 * kk + lane;
        float val;
        if (k < HH)                 val = Wh[k * 2048 + col];
        else if (k < HH + NW)       val = Wx[(3 + k - HH) * 2048 + col];
        else if (k < HH + NW + 3)   val = Wx[(k - (HH + NW)) * 2048 + col];
        else                        val = 0.f;
        sWp[i] = val;
    }
    if (tid < 16) {
        int c_ = tid >> 2, gate = tid & 3;
        sBias[tid] = bvec[(gate << 9) + j0 + c_];
    }
    for (int i = tid; i < HH * 30; i += BLOCK) sWd[i] = Wd[i];
    if (tid < 30) s_bd[tid] = bd[tid];
    __syncthreads();

    // prologue: write x_0 for own batch row, make globally visible
    if (tid < 3) {
        *(float*)((char*)g_inp + a_idx(bb, HH + NW + tid)) =
            strokes[(size_t)bb * TT * 3 + tid];
    }
    unsigned int tgt = GRID;
    grid_barrier(tgt);

    // prime first 2 chunks of each half for t=0 (no free-wait: buffers fresh)
    if (tid == 512) {
        issue_chunk(FU(0, 0), smem_base + OFF_AIN + 0 * CHUNK_BYTES,
                    (const char*)g_inp + 0 * CHUNK_BYTES);
        issue_chunk(FU(0, 1), smem_base + OFF_AIN + 1 * CHUNK_BYTES,
                    (const char*)g_inp + 1 * CHUNK_BYTES);
        issue_chunk(FU(1, 0), smem_base + OFF_AIN + 2 * CHUNK_BYTES,
                    (const char*)g_inp + 10 * CHUNK_BYTES);
        issue_chunk(FU(1, 1), smem_base + OFF_AIN + 3 * CHUNK_BYTES,
                    (const char*)g_inp + 11 * CHUNK_BYTES);
    }

    float c0 = 0.f, c1 = 0.f;            // LSTM c-state (half 0 lanes only)
    int pfull0 = 0, pfull1 = 0;          // compute-warp full parities (per buffer)
    int pfr00 = 0, pfr01 = 0, pfr10 = 0, pfr11 = 0;  // DMA free parities

    // per-warp smem bases for this half's two staging buffers
    const char* sb0 = smem_raw + OFF_AIN + (half * 2 + 0) * CHUNK_BYTES + bloc * 8;
    const char* sb1 = sb0 + CHUNK_BYTES;
    const int kkbase = half * 160;       // first kk row of this half

    for (int t = 0; t < TT; ++t) {
        const char* gin   = (const char*)(g_inp + (t & 1) * GBUF_FLOATS);
        char*       gnext = (char*)(g_inp + ((t + 1) & 1) * GBUF_FLOATS);

        if (isC) {
            // ===== Phase A (compute warps): free-running chunk loop =====
            unsigned long long a00 = 0, a01 = 0, a02 = 0, a03 = 0;  // batch b
            unsigned long long a10 = 0, a11 = 0, a12 = 0, a13 = 0;  // batch b+1

            for (int ci = 0; ci < 10; ++ci) {
                const int s = ci & 1;
                if (s == 0) { mbar_wait(FU(half, 0), pfull0); pfull0 ^= 1; }
                else        { mbar_wait(FU(half, 1), pfull1); pfull1 ^= 1; }

                const char* sb = s ? sb1 : sb0;
                const float* wr0 = sWp + ((kkbase + (ci << 4)) * 32) + cg * 8;
#pragma unroll 4
                for (int j = 0; j < 16; ++j) {
                    ulonglong2 vv = *(const ulonglong2*)(sb + j * 1024);
                    const ulonglong2* wr = (const ulonglong2*)(wr0 + j * 32);
                    ulonglong2 wlo = wr[0], whi = wr[1];   // gates (i,f), (g,o)
                    ffma2(a00, vv.x, wlo.x); ffma2(a01, vv.x, wlo.y);
                    ffma2(a02, vv.x, whi.x); ffma2(a03, vv.x, whi.y);
                    ffma2(a10, vv.y, wlo.x); ffma2(a11, vv.y, wlo.y);
                    ffma2(a12, vv.y, whi.x); ffma2(a13, vv.y, whi.y);
                }
                mbar_arrive(FR(half, s));   // all 32 lanes (free count = 256)
            }

            // stash accumulators for post-join phases
            if (half == 1) {
                // wait for everyone before touching sZ? sZ is a dedicated region,
                // safe to write immediately.
                unsigned long long* zp = sZ + bloc * 16 + cg * 4;
                zp[0] = a00; zp[1] = a01; zp[2] = a02; zp[3] = a03;
                zp += 16;
                zp[0] = a10; zp[1] = a11; zp[2] = a12; zp[3] = a13;
            }
            __syncthreads();             // join all halves + DMA warp

            if (half == 0) {
                const unsigned long long* zp = sZ + bloc * 16 + cg * 4;
                float lo, hi, l2, h2;
#define REDZ(acc, part, bias, dst) { unpack2(acc, lo, hi); unpack2(part, l2, h2); \
                dst = ((lo + l2) + (hi + h2)) + bias; }
                float zi, zf, zg, zo;
                float bi_ = sBias[cg * 4 + 0], bf_ = sBias[cg * 4 + 1];
                float bg_ = sBias[cg * 4 + 2], bo_ = sBias[cg * 4 + 3];

                REDZ(a00, zp[0], bi_, zi); REDZ(a01, zp[1], bf_, zf);
                REDZ(a02, zp[2], bg_, zg); REDZ(a03, zp[3], bo_, zo);
                float cn = sigf(zf) * c0 + sigf(zi) * tanhf(zg);
                float hn = sigf(zo) * tanhf(cn); c0 = cn;
                out[((size_t)bloc * TT + t) * OUT_STRIDE + j0 + cg] = hn;
                *(float*)(gnext + a_idx(bloc, j0 + cg)) = hn;

                zp += 16;
                REDZ(a10, zp[0], bi_, zi); REDZ(a11, zp[1], bf_, zf);
                REDZ(a12, zp[2], bg_, zg); REDZ(a13, zp[3], bo_, zo);
                cn = sigf(zf) * c1 + sigf(zi) * tanhf(zg);
                hn = sigf(zo) * tanhf(cn); c1 = cn;
                out[((size_t)(bloc + 1) * TT + t) * OUT_STRIDE + j0 + cg] = hn;
                *(float*)(gnext + a_idx(bloc + 1, j0 + cg)) = hn;
#undef REDZ
            }
        } else {
            // ===== DMA warp: feed both halves, absorbing all gating =====
            if (tid == 512) {
                const unsigned int wt = (unsigned int)t * GRID;
                int i0 = 2, i1 = 2;
                bool wok = false;
                while (i0 <= 9 || i1 <= 9) {
                    if (i0 <= 9) {
                        int s = i0 & 1;
                        int p = s ? pfr01 : pfr00;
                        if (mbar_test(FR(0, s), p)) {
                            issue_chunk(FU(0, s),
                                        smem_base + OFF_AIN + s * CHUNK_BYTES,
                                        gin + i0 * CHUNK_BYTES);
                            if (s) pfr01 ^= 1; else pfr00 ^= 1;
                            ++i0;
                        }
                    }
                    if (i1 <= 9) {
                        if (!wok && i1 >= 6) {
                            volatile unsigned int* vp = &g_wdone;
                            if (*vp >= wt) { __threadfence(); wok = true; }
                        }
                        if (i1 < 6 || wok) {
                            int s = i1 & 1;
                            int p = s ? pfr11 : pfr10;
                            if (mbar_test(FR(1, s), p)) {
                                issue_chunk(FU(1, s),
                                            smem_base + OFF_AIN + (2 + s) * CHUNK_BYTES,
                                            gin + (10 + i1) * CHUNK_BYTES);
                                if (s) pfr11 ^= 1; else pfr10 ^= 1;
                                ++i1;
                            }
                        }
                    }
                }
            }
            __syncthreads();             // matches compute warps' post-A join
        }
        __threadfence();
        __syncthreads();                 // phase B writes drained

        tgt += GRID;
        grid_barrier(tgt);               // all CTAs' h(t) + gnext h visible

        // DMA warp: prime first 2 chunks per half of step t+1 (overlaps phase C)
        if (tid == 512 && t + 1 < TT) {
            mbar_wait(FR(0, 0), pfr00); pfr00 ^= 1;
            issue_chunk(FU(0, 0), smem_base + OFF_AIN + 0 * CHUNK_BYTES,
                        gnext + 0 * CHUNK_BYTES);
            mbar_wait(FR(0, 1), pfr01); pfr01 ^= 1;
            issue_chunk(FU(0, 1), smem_base + OFF_AIN + 1 * CHUNK_BYTES,
                        gnext + 1 * CHUNK_BYTES);
            mbar_wait(FR(1, 0), pfr10); pfr10 ^= 1;
            issue_chunk(FU(1, 0), smem_base + OFF_AIN + 2 * CHUNK_BYTES,
                        gnext + 10 * CHUNK_BYTES);
            mbar_wait(FR(1, 1), pfr11); pfr11 ^= 1;
            issue_chunk(FU(1, 1), smem_base + OFF_AIN + 3 * CHUNK_BYTES,
                        gnext + 11 * CHUNK_BYTES);
        }

        // ===== Phase C: attention head for batch row bb (overlaps t+1 DMA) =====
        {
            float* orow = out + ((size_t)bb * TT + t) * OUT_STRIDE;

            if (tid < 512) s_h[tid] = orow[tid];
            __syncthreads();

            // y = h @ Wd  (30 outputs, 16-way K split over 480 threads)
            if (tid < 480) {
                int n = tid >> 4, q = tid & 15;
                int k0 = q * 32;
                float p0 = 0.f, p1 = 0.f, p2 = 0.f, p3 = 0.f;
#pragma unroll 4
                for (int k = k0; k < k0 + 32; k += 4) {
                    p0 = fmaf(s_h[k],     sWd[(k)     * 30 + n], p0);
                    p1 = fmaf(s_h[k + 1], sWd[(k + 1) * 30 + n], p1);
                    p2 = fmaf(s_h[k + 2], sWd[(k + 2) * 30 + n], p2);
                    p3 = fmaf(s_h[k + 3], sWd[(k + 3) * 30 + n], p3);
                }
                s_yp[tid] = (p0 + p1) + (p2 + p3);
            }
            __syncthreads();
            if (tid < 30) {
                float s = 0.f;
#pragma unroll
                for (int q = 0; q < 16; ++q) s += s_yp[tid * 16 + q];
                s_y[tid] = __expf(s + s_bd[tid]);
            }
            __syncthreads();
            if (tid < MM) {
                float ka = g_kappa[bb * MM + tid] + s_y[20 + tid];
                g_kappa[bb * MM + tid] = ka;
                s_ka[tid] = ka;
                s_a[tid]  = s_y[tid];
                s_be[tid] = s_y[10 + tid];
            }
            __syncthreads();

            if (tid <= UU) {
                float fu = (float)tid, acc = 0.f;
#pragma unroll
                for (int m = 0; m < MM; ++m) {
                    float d = s_ka[m] - fu;
                    acc = fmaf(s_a[m], __expf(-s_be[m] * d * d), acc);
                }
                s_wf[tid] = acc;
            }
            __syncthreads();

            if (tid < 32) {              // argmax, first-max tie rule
                float bv = -3.4e38f; int bi = 0;
                for (int u = tid; u <= UU; u += 32) {
                    float v = s_wf[u];
                    if (v > bv) { bv = v; bi = u; }
                }
                for (int off = 16; off; off >>= 1) {
                    float ov = __shfl_xor_sync(0xffffffffu, bv, off);
                    int   oi = __shfl_xor_sync(0xffffffffu, bi, off);
                    if (ov > bv || (ov == bv && oi < bi)) { bv = ov; bi = oi; }
                }
                if (tid == 0) orow[HH + NW] = (float)bi;
            }

            // w = wfull[:U] @ transcriptions[bb]   (trans from L2)
            if (tid < NW) {
                const float* tr = trans + (size_t)bb * UU * NW + tid;
                float a0 = 0.f, a1 = 0.f, a2 = 0.f, a3 = 0.f;
#pragma unroll 4
                for (int u = 0; u < UU; u += 4) {
                    a0 = fmaf(s_wf[u],     tr[(u)     * NW], a0);
                    a1 = fmaf(s_wf[u + 1], tr[(u + 1) * NW], a1);
                    a2 = fmaf(s_wf[u + 2], tr[(u + 2) * NW], a2);
                    a3 = fmaf(s_wf[u + 3], tr[(u + 3) * NW], a3);
                }
                float wv = (a0 + a1) + (a2 + a3);
                *(float*)(gnext + a_idx(bb, HH + tid)) = wv;
                orow[HH + tid] = wv;
            }

            // x_{t+1} for own row
            if (t + 1 < TT && tid < 3) {
                *(float*)(gnext + a_idx(bb, HH + NW + tid)) =
                    strokes[(size_t)bb * TT * 3 + (t + 1) * 3 + tid];
            }

            __syncthreads();
            if (tid == 0) {              // signal w_t / x_{t+1} ready
                __threadfence();
                atomicAdd(&g_wdone, 1u);
            }
        }
    }
#undef FU
#undef FR
}

// ---------------- launch ----------------
extern "C" void kernel_launch(void* const* d_in, const int* in_sizes, int n_in,
                              void* d_out, int out_size) {
    const float* strokes = (const float*)d_in[0];
    const float* trans   = (const float*)d_in[1];
    // d_in[2] = enumerated -- recomputed on the fly
    const float* Wx      = (const float*)d_in[3];
    const float* Wh      = (const float*)d_in[4];
    const float* bvec    = (const float*)d_in[5];
    const float* Wd      = (const float*)d_in[6];
    const float* bd      = (const float*)d_in[7];
    float* out = (float*)d_out;

    cudaFuncSetAttribute(rnn_persistent_kernel,
                         cudaFuncAttributeMaxDynamicSharedMemorySize, SMEM_BYTES);

    rnn_init_kernel<<<32, 256>>>();
    rnn_persistent_kernel<<<GRID, BLOCK, SMEM_BYTES>>>(strokes, trans, Wx, Wh,
                                                       bvec, Wd, bd, out);
}